// round 2
// baseline (speedup 1.0000x reference)
#include <cuda_runtime.h>
#include <math.h>

#define B_SZ   4096
#define IN_SZ  1024
#define HID_SZ 1024
#define NAGG   4
#define NOPS   29
#define EPSF   1e-6f

// ---------------- scratch (static device arrays: allocation-free) ----------------
__device__ float g_xp[B_SZ * HID_SZ];                 // 16 MB
__device__ float g_hp[B_SZ * HID_SZ];                 // 16 MB
__device__ float g_agg[(size_t)B_SZ * HID_SZ * NAGG]; // 64 MB

// Resolve scratch destination on-device: keeps kernel_launch free of ANY
// non-launch CUDA API (no cudaGetSymbolAddress -> maximally capture-safe).
__device__ __forceinline__ float* dst_ptr(int sel) {
    return sel == 0 ? g_xp : (sel == 1 ? g_hp : g_agg);
}

// ---------------- fp32 SGEMM: C[m,n] = sum_k A[m,k] * Bw[n,k] (+C) ----------------
// Tiles: 128x128x16, 8x8 per thread, 256 threads.
__global__ __launch_bounds__(256, 2)
void sgemm_nt(int M, int N, int K,
              const float* __restrict__ A, int lda,
              const float* __restrict__ Bw, int ldb,
              int dst_sel, int ldc, int accumulate)
{
    float* __restrict__ C = dst_ptr(dst_sel);

    __shared__ float As[16][136];   // +8 pad: 16B-aligned rows, conflict-free stores
    __shared__ float Bs[16][136];

    const int bm  = blockIdx.y * 128;
    const int bn  = blockIdx.x * 128;
    const int tid = threadIdx.x;
    const int tx  = (tid & 15) << 3;   // 0..120 step 8
    const int ty  = (tid >> 4) << 3;

    float acc[8][8];
#pragma unroll
    for (int i = 0; i < 8; i++)
#pragma unroll
        for (int j = 0; j < 8; j++) acc[i][j] = 0.f;

    for (int k0 = 0; k0 < K; k0 += 16) {
#pragma unroll
        for (int s = 0; s < 2; s++) {
            int slot = tid + s * 256;            // 512 float4 slots per tile
            int row  = slot >> 2;                // 0..127
            int c4   = (slot & 3) << 2;          // 0,4,8,12
            float4 va = *(const float4*)&A [(size_t)(bm + row) * lda + k0 + c4];
            As[c4 + 0][row] = va.x; As[c4 + 1][row] = va.y;
            As[c4 + 2][row] = va.z; As[c4 + 3][row] = va.w;
            float4 vb = *(const float4*)&Bw[(size_t)(bn + row) * ldb + k0 + c4];
            Bs[c4 + 0][row] = vb.x; Bs[c4 + 1][row] = vb.y;
            Bs[c4 + 2][row] = vb.z; Bs[c4 + 3][row] = vb.w;
        }
        __syncthreads();

#pragma unroll
        for (int k = 0; k < 16; k++) {
            float4 a0 = *(const float4*)&As[k][ty];
            float4 a1 = *(const float4*)&As[k][ty + 4];
            float4 b0 = *(const float4*)&Bs[k][tx];
            float4 b1 = *(const float4*)&Bs[k][tx + 4];
            float a[8] = {a0.x, a0.y, a0.z, a0.w, a1.x, a1.y, a1.z, a1.w};
            float b[8] = {b0.x, b0.y, b0.z, b0.w, b1.x, b1.y, b1.z, b1.w};
#pragma unroll
            for (int i = 0; i < 8; i++)
#pragma unroll
                for (int j = 0; j < 8; j++)
                    acc[i][j] = fmaf(a[i], b[j], acc[i][j]);
        }
        __syncthreads();
    }

#pragma unroll
    for (int i = 0; i < 8; i++) {
        float* cp = &C[(size_t)(bm + ty + i) * ldc + bn + tx];
        float4 v0 = make_float4(acc[i][0], acc[i][1], acc[i][2], acc[i][3]);
        float4 v1 = make_float4(acc[i][4], acc[i][5], acc[i][6], acc[i][7]);
        if (accumulate) {
            float4 o0 = *(const float4*)cp;
            float4 o1 = *((const float4*)cp + 1);
            v0.x += o0.x; v0.y += o0.y; v0.z += o0.z; v0.w += o0.w;
            v1.x += o1.x; v1.y += o1.y; v1.z += o1.z; v1.w += o1.w;
        }
        *(float4*)cp       = v0;
        *((float4*)cp + 1) = v1;
    }
}

// ---------------- fused elementwise: 29 ops + gumbel-argmax select ----------------
__device__ __forceinline__ float signf_(float v) {
    return (v > 0.f) ? 1.f : ((v < 0.f) ? -1.f : 0.f);
}

__global__ __launch_bounds__(256)
void fused_ops_kernel(const float* __restrict__ op_weights,
                      const float* __restrict__ constants,
                      const float* __restrict__ edge_weights,
                      const float* __restrict__ gumbel,
                      float* __restrict__ out)
{
    const int idx = blockIdx.x * 256 + threadIdx.x;   // b*HID + j
    const int j = idx & (HID_SZ - 1);
    const int b = idx >> 10;

    const float xp = g_xp[idx];
    const float hp = g_hp[idx];
    const float c  = __ldg(&constants[j]);

    float w[4];
#pragma unroll
    for (int a = 0; a < 4; a++)
        w[a] = g_agg[((size_t)b << 12) + (j << 2) + a] * __ldg(&edge_weights[(j << 2) + a]);

    float ops[NOPS];
    const float x2  = xp * xp;
    const float axp = fabsf(xp);
    ops[0]  = xp;
    ops[1]  = xp + c;
    ops[2]  = xp * c;
    ops[3]  = x2;
    ops[4]  = x2 * xp;
    ops[5]  = sqrtf(axp + EPSF);
    ops[6]  = axp;
    ops[7]  = -xp;
    ops[8]  = sinf(xp);
    ops[9]  = cosf(xp);
    ops[10] = tanhf(xp);
    ops[11] = 1.f / (1.f + expf(-xp));
    ops[12] = expf(fminf(fmaxf(xp, -10.f), 10.f));
    ops[13] = logf(axp + EPSF);
    ops[14] = 1.f / (xp + EPSF * signf_(xp + 1e-9f));
    ops[15] = xp + hp;
    ops[16] = xp - hp;
    ops[17] = xp * hp;
    ops[18] = xp / (hp + EPSF * signf_(hp + 1e-9f));
    ops[19] = fmaxf(xp, hp);
    ops[20] = fminf(xp, hp);
    {
        const float pw = fminf(fmaxf(hp, -3.f), 3.f);
        ops[21] = signf_(xp) * powf(axp + EPSF, pw);
    }
    {
        const float sum  = w[0] + w[1] + w[2] + w[3];
        const float mean = sum * 0.25f;
        float prod = 1.f;
#pragma unroll
        for (int a = 0; a < 4; a++)
            prod *= fminf(fmaxf(w[a], -10.f), 10.f);
        const float d0 = w[0] - mean, d1 = w[1] - mean, d2 = w[2] - mean, d3 = w[3] - mean;
        const float var = (d0*d0 + d1*d1 + d2*d2 + d3*d3) * (1.f / 3.f);
        ops[22] = sum;
        ops[23] = mean;
        ops[24] = prod;
        ops[25] = fmaxf(fmaxf(w[0], w[1]), fmaxf(w[2], w[3]));
        ops[26] = fminf(fminf(w[0], w[1]), fminf(w[2], w[3]));
        ops[27] = sqrtf(var) + 1e-6f;
        ops[28] = sqrtf(w[0]*w[0] + w[1]*w[1] + w[2]*w[2] + w[3]*w[3]);
    }

    // hard gumbel select == argmax(op_weights + gumbel); first-max tie-break like jnp.argmax
    const float* __restrict__ gr = gumbel + (size_t)idx * NOPS;
    const float* __restrict__ ow = op_weights + j * NOPS;
    float best = __ldg(&ow[0]) + __ldg(&gr[0]);
    int   karg = 0;
#pragma unroll
    for (int o = 1; o < NOPS; o++) {
        float v = __ldg(&ow[o]) + __ldg(&gr[o]);
        if (v > best) { best = v; karg = o; }
    }

    float r = ops[0];
#pragma unroll
    for (int o = 1; o < NOPS; o++)
        r = (karg == o) ? ops[o] : r;

    out[idx] = fminf(fmaxf(r, -100.f), 100.f);
}

// ---------------- entropy of softmax(op_weights), mean over HID rows ----------------
__global__ void entropy_kernel(const float* __restrict__ ow, float* __restrict__ dst)
{
    const int j = threadIdx.x;   // 1024 threads, one row each
    const float* r = ow + j * NOPS;
    float m = -1e30f;
#pragma unroll
    for (int o = 0; o < NOPS; o++) m = fmaxf(m, r[o]);
    float s = 0.f;
#pragma unroll
    for (int o = 0; o < NOPS; o++) s += expf(r[o] - m);
    const float inv = 1.f / s;
    float ent = 0.f;
#pragma unroll
    for (int o = 0; o < NOPS; o++) {
        float p = expf(r[o] - m) * inv;
        ent -= p * logf(p + 1e-10f);
    }
    __shared__ float red[32];
#pragma unroll
    for (int o = 16; o; o >>= 1) ent += __shfl_xor_sync(0xffffffffu, ent, o);
    if ((j & 31) == 0) red[j >> 5] = ent;
    __syncthreads();
    if (j < 32) {
        float v = red[j];
#pragma unroll
        for (int o = 16; o; o >>= 1) v += __shfl_xor_sync(0xffffffffu, v, o);
        if (j == 0) dst[0] = v * (1.f / (float)HID_SZ);
    }
}

// ---------------- launch: pure kernel launches, nothing else ----------------
extern "C" void kernel_launch(void* const* d_in, const int* in_sizes, int n_in,
                              void* d_out, int out_size)
{
    const float* x            = (const float*)d_in[0];
    const float* h            = (const float*)d_in[1];
    const float* op_weights   = (const float*)d_in[2];
    const float* constants    = (const float*)d_in[3];
    const float* W_in         = (const float*)d_in[4];
    const float* W_h          = (const float*)d_in[5];
    const float* edge_weights = (const float*)d_in[6];
    const float* W_agg        = (const float*)d_in[7];
    const float* gumbel       = (const float*)d_in[8];
    float* out = (float*)d_out;

    // xp = x @ W_in^T   (4096 x 1024 x 1024)
    sgemm_nt<<<dim3(HID_SZ / 128, B_SZ / 128), 256>>>(
        B_SZ, HID_SZ, IN_SZ, x, IN_SZ, W_in, IN_SZ, /*dst=*/0, HID_SZ, 0);
    // hp = h @ W_h^T
    sgemm_nt<<<dim3(HID_SZ / 128, B_SZ / 128), 256>>>(
        B_SZ, HID_SZ, HID_SZ, h, HID_SZ, W_h, HID_SZ, /*dst=*/1, HID_SZ, 0);
    // agg = [x,h] @ W_agg^T, split over K: x part then h part (accumulate)
    sgemm_nt<<<dim3((HID_SZ * NAGG) / 128, B_SZ / 128), 256>>>(
        B_SZ, HID_SZ * NAGG, IN_SZ, x, IN_SZ, W_agg, IN_SZ + HID_SZ, /*dst=*/2, HID_SZ * NAGG, 0);
    sgemm_nt<<<dim3((HID_SZ * NAGG) / 128, B_SZ / 128), 256>>>(
        B_SZ, HID_SZ * NAGG, HID_SZ, h, HID_SZ, W_agg + IN_SZ, IN_SZ + HID_SZ, /*dst=*/2, HID_SZ * NAGG, 1);

    fused_ops_kernel<<<(B_SZ * HID_SZ) / 256, 256>>>(
        op_weights, constants, edge_weights, gumbel, out);

    if (out_size > B_SZ * HID_SZ)
        entropy_kernel<<<1, HID_SZ>>>(op_weights, out + (size_t)B_SZ * HID_SZ);
}